// round 9
// baseline (speedup 1.0000x reference)
#include <cuda_runtime.h>
#include <cstdint>

// Problem constants (fixed by the reference setup)
#define NB 65536        // batch rows
#define NF 512          // in_features
#define NK 1299         // number of centers
#define CAP 256         // per-bin capacity (mean 50.4, sigma 7.1 -> 29 sigma headroom)
#define SPLIT 4         // sub-blocks per center (occupancy / wave balance)
#define K2_BLOCKS (NK * SPLIT)
#define THREADS 256
#define WPB (THREADS / 32)

// Fixed-point loss accumulator: integer atomics commute exactly -> bit-deterministic.
#define LOSS_SCALE 1073741824.0f   // 2^30
__device__ unsigned long long g_loss_acc;   // zero-init; reset by last block
__device__ unsigned int      g_ticket;      // zero-init; reset by last block
__device__ int               g_cnt[NK];     // zero-init; reset by last block
__device__ int               g_rowidx[NK * CAP];

// K1: bin row indices by label. Order within a bin is nondeterministic, but every
// row's output is computed identically and the loss sum is integer-commutative,
// so results are bit-identical regardless of binning order.
__global__ __launch_bounds__(256)
void bin_kernel(const int* __restrict__ label)
{
    int b = blockIdx.x * 256 + threadIdx.x;
    int k = label[b];
    k = (k < 0) ? 0 : (k >= NK ? NK - 1 : k);          // in-bounds insurance
    int pos = atomicAdd(&g_cnt[k], 1);
    if (pos < CAP) g_rowidx[k * CAP + pos] = b;
}

// K2: block (k, s) handles rows i = s, s+4, ... of bin k; warp per row.
// The single 2KB center row becomes L1-resident -> centers LTS traffic ~10MB
// instead of 128MB; kernel becomes DRAM-bound on the input stream.
__global__ __launch_bounds__(THREADS)
void predict_kernel(const float* __restrict__ input,
                    const float* __restrict__ factor,
                    const float* __restrict__ centers,
                    float* __restrict__ out)           // out[0]=loss, out[1..NB]=pred
{
    const int k    = blockIdx.x / SPLIT;
    const int s    = blockIdx.x % SPLIT;
    const int warp = threadIdx.x >> 5;
    const int lane = threadIdx.x & 31;

    int n = g_cnt[k];
    if (n > CAP) n = CAP;

    const float4* ce4 = reinterpret_cast<const float4*>(centers + (size_t)k * NF);

    float lloss = 0.0f;   // meaningful in lane 0 only

    for (int i = s + SPLIT * warp; i < n; i += SPLIT * WPB) {
        int b = g_rowidx[k * CAP + i];                 // broadcast load
        const float4* in4 = reinterpret_cast<const float4*>(input + (size_t)b * NF);
        float acc = 0.0f;
#pragma unroll
        for (int j = 0; j < 4; j++) {
            float4 a = __ldcg(&in4[lane + 32 * j]);    // streamed, bypass L1
            float4 w = ce4[lane + 32 * j];             // L1-resident center
            acc += a.x * w.x + a.y * w.y + a.z * w.z + a.w * w.w;
        }
#pragma unroll
        for (int o = 16; o; o >>= 1)
            acc += __shfl_xor_sync(0xffffffffu, acc, o);
        if (lane == 0) {
            float p = 12.0f * tanhf(acc);
            __stcg(&out[1 + b], p);
            float d = p - factor[b];
            float ad = fabsf(d);
            lloss += (ad < 1.0f) ? 0.5f * d * d : (ad - 0.5f);
        }
    }

    __shared__ float s_loss[WPB];
    __shared__ bool  s_last;
    if (lane == 0) s_loss[warp] = lloss;
    __syncthreads();

    if (threadIdx.x == 0) {
        float t = 0.0f;
#pragma unroll
        for (int i = 0; i < WPB; i++) t += s_loss[i];
        unsigned long long q = (unsigned long long)(t * LOSS_SCALE + 0.5f);
        unsigned long long old = atomicAdd(&g_loss_acc, q);
        // Data dependency (old>>63 is provably 0: sum < 2^50) forces the ticket
        // bump to issue only after the loss-add has completed at L2. No fence,
        // no L1 flush.
        unsigned int dep = (unsigned int)(old >> 63);
        unsigned int ticket = atomicAdd(&g_ticket, 1u + dep);
        s_last = (ticket == (unsigned int)(K2_BLOCKS - 1));
    }
    __syncthreads();

    // Last block: publish loss and reset all scratch state for graph replay.
    // Safe: every block read g_cnt[k] before bumping its ticket.
    if (s_last) {
        for (int i = threadIdx.x; i < NK; i += THREADS)
            g_cnt[i] = 0;
        if (threadIdx.x == 0) {
            unsigned long long total = atomicAdd(&g_loss_acc, 0ull);
            out[0] = (float)((double)total * (1.0 / ((double)LOSS_SCALE * (double)NB)));
            g_loss_acc = 0ull;
            g_ticket   = 0u;
        }
    }
}

extern "C" void kernel_launch(void* const* d_in, const int* in_sizes, int n_in,
                              void* d_out, int out_size)
{
    // metadata order follows setup_inputs: input, factor, label, centers
    const float* input   = (const float*)d_in[0];
    const float* factor  = (const float*)d_in[1];
    const int*   label   = (const int*)d_in[2];
    const float* centers = (const float*)d_in[3];

    float* out = (float*)d_out;   // out[0]=loss, out[1..NB]=predict_a

    bin_kernel<<<NB / 256, 256>>>(label);
    predict_kernel<<<K2_BLOCKS, THREADS>>>(input, factor, centers, out);
}

// round 10
// speedup vs baseline: 1.3246x; 1.3246x over previous
#include <cuda_runtime.h>
#include <cstdint>

// Problem constants (fixed by the reference setup)
#define NB 65536        // batch rows
#define NF 512          // in_features
#define NK 1299         // number of centers
#define WARPS_PER_BLOCK 8
#define NBLOCKS (NB / WARPS_PER_BLOCK)   // 8192 blocks, 1 warp per row

// Fixed-point loss accumulator: integer atomics commute exactly -> result is
// bit-deterministic regardless of block scheduling order.
// Partials >= 0, <= ~128; scale 2^30 => max total ~2^50 < 2^63.
#define LOSS_SCALE 1073741824.0f   // 2^30
__device__ unsigned long long g_loss_acc;   // zero-init; reset by last block
__device__ unsigned int      g_ticket;      // zero-init; reset by last block

// Per-row gathered dot product + tanh + smooth-L1, fused deterministic loss.
// One warp per row: 512 floats = 128 float4 = 4 float4 per lane.
// Loop body identical to the proven ~24.7us round-7 kernel.
__global__ __launch_bounds__(WARPS_PER_BLOCK * 32)
void predict_kernel(const float* __restrict__ input,
                    const float* __restrict__ factor,
                    const int* __restrict__ label,     // JAX downcasts int64->int32
                    const float* __restrict__ centers,
                    float* __restrict__ out)           // out[0]=loss, out[1..NB]=pred
{
    const int warp = threadIdx.x >> 5;
    const int lane = threadIdx.x & 31;
    const int b = blockIdx.x * WARPS_PER_BLOCK + warp;

    const float4* in4 = reinterpret_cast<const float4*>(input + (size_t)b * NF);
    int c = label[b];
    c = (c < 0) ? 0 : (c >= NK ? NK - 1 : c);          // in-bounds insurance
    const float4* ce4 = reinterpret_cast<const float4*>(centers + (size_t)c * NF);

    // input: zero reuse -> bypass L1 (__ldcg); centers: default (L1-cached).
    float acc = 0.0f;
#pragma unroll
    for (int i = 0; i < 4; i++) {
        float4 a = __ldcg(&in4[lane + 32 * i]);
        float4 w = ce4[lane + 32 * i];
        acc += a.x * w.x + a.y * w.y + a.z * w.z + a.w * w.w;
    }

#pragma unroll
    for (int o = 16; o; o >>= 1)
        acc += __shfl_xor_sync(0xffffffffu, acc, o);

    __shared__ float s_loss[WARPS_PER_BLOCK];
    __shared__ bool  s_last;
    if (lane == 0) {
        float p = 12.0f * tanhf(acc);
        __stcg(&out[1 + b], p);                        // streamed output, skip L1
        float d = p - factor[b];
        float ad = fabsf(d);
        s_loss[warp] = (ad < 1.0f) ? 0.5f * d * d : (ad - 0.5f);
    }
    __syncthreads();

    if (threadIdx.x == 0) {
        float t = 0.0f;
#pragma unroll
        for (int i = 0; i < WARPS_PER_BLOCK; i++) t += s_loss[i];
        // Relaxed fixed-point accumulation (proven free in the hot kernel).
        unsigned long long q  = (unsigned long long)(t * LOSS_SCALE + 0.5f);
        unsigned long long old = atomicAdd(&g_loss_acc, q);
        // True data dependency: dep == 0 always (sum < 2^50), but the HW must
        // complete the loss-add (get `old` back from L2) before the ticket add
        // can issue. Orders add -> ticket with NO fence / acquire / L1 flush.
        unsigned int dep = (unsigned int)(old >> 63);
        unsigned int ticket = atomicAdd(&g_ticket, 1u + dep);
        s_last = (ticket == (unsigned int)(NBLOCKS - 1));
    }
    __syncthreads();

    // Last block (all 8192 loss-adds have reached L2): publish + reset state.
    if (s_last && threadIdx.x == 0) {
        unsigned long long total = atomicAdd(&g_loss_acc, 0ull);  // L2-coherent read
        out[0] = (float)((double)total * (1.0 / ((double)LOSS_SCALE * (double)NB)));
        g_loss_acc = 0ull;                              // clean state for next replay
        g_ticket   = 0u;
    }
}

extern "C" void kernel_launch(void* const* d_in, const int* in_sizes, int n_in,
                              void* d_out, int out_size)
{
    // metadata order follows setup_inputs: input, factor, label, centers
    const float* input   = (const float*)d_in[0];
    const float* factor  = (const float*)d_in[1];
    const int*   label   = (const int*)d_in[2];
    const float* centers = (const float*)d_in[3];

    float* out = (float*)d_out;   // out[0]=loss, out[1..NB]=predict_a

    predict_kernel<<<NBLOCKS, WARPS_PER_BLOCK * 32>>>(input, factor, label, centers, out);
}

// round 11
// speedup vs baseline: 1.3811x; 1.0427x over previous
#include <cuda_runtime.h>
#include <cstdint>

// Problem constants (fixed by the reference setup)
#define NB 65536        // batch rows
#define NF 512          // in_features
#define NK 1299         // number of centers
#define WARPS_PER_BLOCK 8
#define ROWS_PER_WARP 2
#define ROWS_PER_BLOCK (WARPS_PER_BLOCK * ROWS_PER_WARP)   // 16
#define NBLOCKS (NB / ROWS_PER_BLOCK)                      // 4096

// Fixed-point loss accumulator: integer adds commute exactly -> deterministic.
// IMPORTANT: the atomicAdd return value is NOT used -> compiles to REDG
// (no-return reduction), which round 7 proved is free in the hot kernel.
#define LOSS_SCALE 1073741824.0f   // 2^30
__device__ unsigned long long g_loss_acc;   // zero-init; finisher resets it

// Kernel 1: warp handles 2 consecutive rows. All 8 input (DRAM) loads issued
// front-batched for MLP=8 on the long-latency path; centers (L2/L1 hits)
// consumed after. Input stays perfectly sequential across the grid.
__global__ __launch_bounds__(WARPS_PER_BLOCK * 32)
void predict_kernel(const float* __restrict__ input,
                    const float* __restrict__ factor,
                    const int* __restrict__ label,     // JAX downcasts int64->int32
                    const float* __restrict__ centers,
                    float* __restrict__ pred_out)      // points at d_out+1
{
    const int warp = threadIdx.x >> 5;
    const int lane = threadIdx.x & 31;
    const int b0 = (blockIdx.x * WARPS_PER_BLOCK + warp) * ROWS_PER_WARP;
    const int b1 = b0 + 1;

    const float4* in0 = reinterpret_cast<const float4*>(input + (size_t)b0 * NF);
    const float4* in1 = reinterpret_cast<const float4*>(input + (size_t)b1 * NF);

    int c0 = label[b0], c1 = label[b1];
    c0 = (c0 < 0) ? 0 : (c0 >= NK ? NK - 1 : c0);
    c1 = (c1 < 0) ? 0 : (c1 >= NK ? NK - 1 : c1);
    const float4* ce0 = reinterpret_cast<const float4*>(centers + (size_t)c0 * NF);
    const float4* ce1 = reinterpret_cast<const float4*>(centers + (size_t)c1 * NF);

    // Front-batch the 8 DRAM loads (input, zero reuse -> bypass L1).
    float4 a00 = __ldcg(&in0[lane +  0]);
    float4 a01 = __ldcg(&in0[lane + 32]);
    float4 a02 = __ldcg(&in0[lane + 64]);
    float4 a03 = __ldcg(&in0[lane + 96]);
    float4 a10 = __ldcg(&in1[lane +  0]);
    float4 a11 = __ldcg(&in1[lane + 32]);
    float4 a12 = __ldcg(&in1[lane + 64]);
    float4 a13 = __ldcg(&in1[lane + 96]);

    // Centers: short-latency L2/L1 hits, issued after.
    float4 w00 = ce0[lane +  0];
    float4 w01 = ce0[lane + 32];
    float4 w02 = ce0[lane + 64];
    float4 w03 = ce0[lane + 96];
    float4 w10 = ce1[lane +  0];
    float4 w11 = ce1[lane + 32];
    float4 w12 = ce1[lane + 64];
    float4 w13 = ce1[lane + 96];

    float acc0 = a00.x*w00.x + a00.y*w00.y + a00.z*w00.z + a00.w*w00.w
               + a01.x*w01.x + a01.y*w01.y + a01.z*w01.z + a01.w*w01.w
               + a02.x*w02.x + a02.y*w02.y + a02.z*w02.z + a02.w*w02.w
               + a03.x*w03.x + a03.y*w03.y + a03.z*w03.z + a03.w*w03.w;
    float acc1 = a10.x*w10.x + a10.y*w10.y + a10.z*w10.z + a10.w*w10.w
               + a11.x*w11.x + a11.y*w11.y + a11.z*w11.z + a11.w*w11.w
               + a12.x*w12.x + a12.y*w12.y + a12.z*w12.z + a12.w*w12.w
               + a13.x*w13.x + a13.y*w13.y + a13.z*w13.z + a13.w*w13.w;

#pragma unroll
    for (int o = 16; o; o >>= 1) {
        acc0 += __shfl_xor_sync(0xffffffffu, acc0, o);
        acc1 += __shfl_xor_sync(0xffffffffu, acc1, o);
    }

    __shared__ float s_loss[WARPS_PER_BLOCK];
    if (lane == 0) {
        float p0 = 12.0f * tanhf(acc0);
        float p1 = 12.0f * tanhf(acc1);
        __stcg(&pred_out[b0], p0);
        __stcg(&pred_out[b1], p1);
        float d0 = p0 - factor[b0];
        float d1 = p1 - factor[b1];
        float ad0 = fabsf(d0), ad1 = fabsf(d1);
        float l0 = (ad0 < 1.0f) ? 0.5f * d0 * d0 : (ad0 - 0.5f);
        float l1 = (ad1 < 1.0f) ? 0.5f * d1 * d1 : (ad1 - 0.5f);
        s_loss[warp] = l0 + l1;
    }
    __syncthreads();

    if (threadIdx.x == 0) {
        float t = 0.0f;
#pragma unroll
        for (int i = 0; i < WARPS_PER_BLOCK; i++) t += s_loss[i];
        unsigned long long q = (unsigned long long)(t * LOSS_SCALE + 0.5f);
        atomicAdd(&g_loss_acc, q);   // return unused -> REDG, no return trip
    }
}

// Kernel 2: trivial finisher — scale the fixed-point sum, reset accumulator.
__global__ void loss_finish_kernel(float* __restrict__ out)
{
    unsigned long long q = g_loss_acc;
    out[0] = (float)((double)q * (1.0 / ((double)LOSS_SCALE * (double)NB)));
    g_loss_acc = 0ull;                                 // clean state for next replay
}

extern "C" void kernel_launch(void* const* d_in, const int* in_sizes, int n_in,
                              void* d_out, int out_size)
{
    // metadata order follows setup_inputs: input, factor, label, centers
    const float* input   = (const float*)d_in[0];
    const float* factor  = (const float*)d_in[1];
    const int*   label   = (const int*)d_in[2];
    const float* centers = (const float*)d_in[3];

    float* out = (float*)d_out;   // out[0]=loss, out[1..NB]=predict_a
    float* pred_out = out + 1;

    predict_kernel<<<NBLOCKS, WARPS_PER_BLOCK * 32>>>(input, factor, label, centers, pred_out);
    loss_finish_kernel<<<1, 1>>>(out);
}

// round 12
// speedup vs baseline: 1.4186x; 1.0271x over previous
#include <cuda_runtime.h>
#include <cstdint>

// Problem constants (fixed by the reference setup)
#define NB 65536        // batch rows
#define NF 512          // in_features
#define NK 1299         // number of centers
#define WARPS_PER_BLOCK 8
#define NBLOCKS (NB / WARPS_PER_BLOCK)   // 8192 blocks, 1 warp per row

// Fixed-point loss accumulator: integer adds commute exactly -> deterministic.
// atomicAdd return value unused -> REDG (no-return), proven free in hot kernel.
#define LOSS_SCALE 1073741824.0f   // 2^30
__device__ unsigned long long g_loss_acc;   // zero-init; finisher resets it

// Kernel 1: per-row gathered dot product + tanh + smooth-L1 term.
// One warp per row (MLP_p1=4) — proven fastest config (24.7us). FROZEN.
__global__ __launch_bounds__(WARPS_PER_BLOCK * 32)
void predict_kernel(const float* __restrict__ input,
                    const float* __restrict__ factor,
                    const int* __restrict__ label,     // JAX downcasts int64->int32
                    const float* __restrict__ centers,
                    float* __restrict__ pred_out)      // points at d_out+1
{
    const int warp = threadIdx.x >> 5;
    const int lane = threadIdx.x & 31;
    const int b = blockIdx.x * WARPS_PER_BLOCK + warp;

    const float4* in4 = reinterpret_cast<const float4*>(input + (size_t)b * NF);
    int c = label[b];
    c = (c < 0) ? 0 : (c >= NK ? NK - 1 : c);          // in-bounds insurance
    const float4* ce4 = reinterpret_cast<const float4*>(centers + (size_t)c * NF);

    // input: zero reuse -> bypass L1 (__ldcg), keep L1 capacity for centers.
    float acc = 0.0f;
#pragma unroll
    for (int i = 0; i < 4; i++) {
        float4 a = __ldcg(&in4[lane + 32 * i]);
        float4 w = ce4[lane + 32 * i];
        acc += a.x * w.x + a.y * w.y + a.z * w.z + a.w * w.w;
    }

#pragma unroll
    for (int o = 16; o; o >>= 1)
        acc += __shfl_xor_sync(0xffffffffu, acc, o);

    __shared__ float s_loss[WARPS_PER_BLOCK];
    if (lane == 0) {
        float p = 12.0f * tanhf(acc);
        __stcg(&pred_out[b], p);                       // streamed output, skip L1
        float d = p - factor[b];
        float ad = fabsf(d);
        s_loss[warp] = (ad < 1.0f) ? 0.5f * d * d : (ad - 0.5f);
    }
    __syncthreads();

    if (threadIdx.x == 0) {
        float t = 0.0f;
#pragma unroll
        for (int i = 0; i < WARPS_PER_BLOCK; i++) t += s_loss[i];
        unsigned long long q = (unsigned long long)(t * LOSS_SCALE + 0.5f);
        atomicAdd(&g_loss_acc, q);   // return unused -> REDG, no return trip
    }
}

// Kernel 2: trivial finisher. With PDL it launches while predict drains;
// cudaGridDependencySynchronize() guarantees all loss REDGs are visible.
__global__ void loss_finish_kernel(float* __restrict__ out)
{
#if __CUDA_ARCH__ >= 900
    cudaGridDependencySynchronize();
#endif
    unsigned long long q = g_loss_acc;
    out[0] = (float)((double)q * (1.0 / ((double)LOSS_SCALE * (double)NB)));
    g_loss_acc = 0ull;                                 // clean state for next replay
}

extern "C" void kernel_launch(void* const* d_in, const int* in_sizes, int n_in,
                              void* d_out, int out_size)
{
    // metadata order follows setup_inputs: input, factor, label, centers
    const float* input   = (const float*)d_in[0];
    const float* factor  = (const float*)d_in[1];
    const int*   label   = (const int*)d_in[2];
    const float* centers = (const float*)d_in[3];

    float* out = (float*)d_out;   // out[0]=loss, out[1..NB]=predict_a
    float* pred_out = out + 1;

    predict_kernel<<<NBLOCKS, WARPS_PER_BLOCK * 32>>>(input, factor, label, centers, pred_out);

    // PDL launch of the finisher: overlap its launch latency with predict's tail.
    cudaLaunchConfig_t cfg = {};
    cfg.gridDim  = dim3(1, 1, 1);
    cfg.blockDim = dim3(1, 1, 1);
    cfg.dynamicSmemBytes = 0;
    cfg.stream = 0;   // same (legacy default) stream as predict_kernel
    cudaLaunchAttribute attr[1];
    attr[0].id = cudaLaunchAttributeProgrammaticStreamSerialization;
    attr[0].val.programmaticStreamSerializationAllowed = 1;
    cfg.attrs = attr;
    cfg.numAttrs = 1;

    cudaError_t e = cudaLaunchKernelEx(&cfg, loss_finish_kernel, out);
    if (e != cudaSuccess) {
        // Fallback: plain serialized launch (reproduces the proven 29.2us path).
        loss_finish_kernel<<<1, 1>>>(out);
    }
}